// round 3
// baseline (speedup 1.0000x reference)
#include <cuda_runtime.h>
#include <math.h>

// ---------------------------------------------------------------------------
// FastConvLSTM restructured:
//   enc  = relu((x @ W1c)*bn_s + b1)                      [B*T, 64]
//   pre_i(b,t) = enc @ Qi + bias_i      (gate i: x-only, group 0)
//   pre_f(b,t) = enc @ Qf + h[0:512]   @ Wf + bias_f      (group 1)
//   pre_o(b,t) =           h[512:1280] @ Wo + bias_o      (group 2, h-only)
//   pre_g(b,t) =           h[1280:2048]@ Wg + bias_g      (group 3, h-only)
//   c = sig(pre_f)*c + sig(pre_i)*tanh(pre_g); h = sig(pre_o)*tanh(c)
// h/c are [B, 128ch*16spatial] = [2048, 2048], spatial flattened (y*4+x).
// ---------------------------------------------------------------------------

#define BATCH 2048
#define TSTEPS 128
#define FEAT 84
#define BT (BATCH * TSTEPS)

__device__ __align__(128) float g_W1[FEAT * 64];
__device__ __align__(128) float g_b1[64];
__device__ __align__(128) float g_S[1024 * 64];        // S[o][c]
__device__ __align__(128) float g_Q[64 * 4096];        // rows c, cols [0,2048)=i, [2048,4096)=f
__device__ __align__(128) float g_bias_if[4096];
__device__ __align__(128) float g_Wf[512 * 2048];      // [k][j]
__device__ __align__(128) float g_Wo[768 * 2048];
__device__ __align__(128) float g_Wg[768 * 2048];
__device__ __align__(128) float g_bias_o[2048];
__device__ __align__(128) float g_bias_g[2048];
__device__ __align__(128) float g_enc[(size_t)BT * 64];
__device__ __align__(128) float g_h[2][(size_t)BATCH * 2048];
__device__ __align__(128) float g_c[(size_t)BATCH * 2048];
__device__ __align__(128) float g_hid[(size_t)BATCH * 128];

// ---------------- weight prep kernels (run every launch; cheap) ----------------

__global__ void k_prep_w1(const float* __restrict__ cw, const float* __restrict__ cb,
                          const float* __restrict__ gam, const float* __restrict__ bet,
                          const float* __restrict__ mean, const float* __restrict__ var) {
    int i = blockIdx.x * blockDim.x + threadIdx.x;
    if (i >= FEAT * 64) return;
    int f = i / 64, c = i % 64;
    float s = gam[c] * rsqrtf(var[c] + 1e-5f);
    g_W1[f * 64 + c] = cw[c * (FEAT * 3) + f * 3 + 1] * s;   // center tap only
    if (f == 0) g_b1[c] = (cb[c] - mean[c]) * s + bet[c];
}

__global__ void k_S(const float* __restrict__ lin_w) {
    int idx = blockIdx.x * blockDim.x + threadIdx.x;
    if (idx >= 1024 * 64) return;
    int o = idx >> 6, c = idx & 63;
    float s = 0.f;
#pragma unroll
    for (int j = 0; j < 16; j++) s += lin_w[(size_t)o * 1024 + (c << 4) + j];
    g_S[idx] = s;
}

// Qi/Qf: fold Linear into the x-side of the grouped conv.
__global__ void k_buildQ(const float* __restrict__ cell_w, const float* __restrict__ cell_b,
                         const float* __restrict__ lin_b) {
    int idx = blockIdx.x * blockDim.x + threadIdx.x;
    if (idx >= 4096 * 64) return;
    int j = idx / 64, c = idx % 64;
    int gate = j / 2048;               // 0 = i, 1 = f(x part)
    int jj = j % 2048;
    int co = jj / 16, p = jj % 16;
    int py = p / 4, px = p % 4;
    int wco = (gate == 0) ? co : 128 + co;
    int nci = (gate == 0) ? 48 : 16;
    float acc = 0.f, bacc = 0.f;
    for (int ci = 0; ci < nci; ci++) {
        int xch = (gate == 0) ? ci : 48 + ci;  // x_t channel feeding this tap
        for (int ky = 0; ky < 3; ky++) {
            int qy = py + ky - 1; if (qy < 0 || qy > 3) continue;
            for (int kx = 0; kx < 3; kx++) {
                int qx = px + kx - 1; if (qx < 0 || qx > 3) continue;
                float w = cell_w[(size_t)wco * 432 + ci * 9 + ky * 3 + kx];
                int o = xch * 16 + qy * 4 + qx;
                acc += w * g_S[o * 64 + c];
                if (c == 0) bacc += w * lin_b[o];
            }
        }
    }
    g_Q[(size_t)c * 4096 + j] = acc;
    if (c == 0) g_bias_if[j] = cell_b[wco] + bacc;
}

// Dense-equivalent recurrent weights for gates f/o/g (spatial flattened).
__global__ void k_buildWh(const float* __restrict__ cell_w, const float* __restrict__ cell_b) {
    size_t idx = (size_t)blockIdx.x * blockDim.x + threadIdx.x;
    if (idx >= (size_t)2048 * 2048) return;
    int j = (int)(idx % 2048);
    int r = (int)(idx / 2048);         // 0..2047 rows across f(512) | o(768) | g(768)
    int co = j / 16, p = j % 16, py = p / 4, px = p % 4;
    float* dst; int wco, lin;
    if (r < 512)        { dst = &g_Wf[(size_t)r * 2048 + j];          wco = 128 + co; lin = 16 + r / 16; }
    else if (r < 1280)  { int rr = r - 512;  dst = &g_Wo[(size_t)rr * 2048 + j]; wco = 256 + co; lin = rr / 16; }
    else                { int rr = r - 1280; dst = &g_Wg[(size_t)rr * 2048 + j]; wco = 384 + co; lin = rr / 16; }
    int q = r % 16, qy = q / 4, qx = q % 4;
    int ky = qy - py + 1, kx = qx - px + 1;
    float v = 0.f;
    if (ky >= 0 && ky < 3 && kx >= 0 && kx < 3)
        v = cell_w[(size_t)wco * 432 + lin * 9 + ky * 3 + kx];
    *dst = v;
    if (r == 0) g_bias_o[j] = cell_b[256 + co];
    if (r == 1) g_bias_g[j] = cell_b[384 + co];
}

// ---------------- encoder: enc = relu(x @ W1 + b1) ----------------

__global__ void k_enc(const float* __restrict__ x) {
    __shared__ float sW[FEAT * 64];
    __shared__ float sb[64];
    __shared__ float sx[32][FEAT];
    int tid = threadIdx.x;
    for (int i = tid; i < FEAT * 64; i += 256) sW[i] = g_W1[i];
    if (tid < 64) sb[tid] = g_b1[tid];
    size_t row0 = (size_t)blockIdx.x * 32;
    for (int i = tid; i < 32 * FEAT; i += 256) {
        int r = i / FEAT, f = i % FEAT;
        sx[r][f] = x[(row0 + r) * FEAT + f];
    }
    __syncthreads();
    int c = tid & 63;
    int rg = tid >> 6;                 // 4 groups x 8 rows
    for (int rr = 0; rr < 8; rr++) {
        int r = rg * 8 + rr;
        float acc = sb[c];
#pragma unroll 4
        for (int f = 0; f < FEAT; f++) acc += sx[r][f] * sW[f * 64 + c];
        g_enc[(row0 + r) * 64 + c] = fmaxf(acc, 0.f);
    }
}

__global__ void k_zero() {
    size_t i = (size_t)blockIdx.x * blockDim.x + threadIdx.x;
    if (i < (size_t)BATCH * 2048) { g_h[0][i] = 0.f; g_c[i] = 0.f; }
}

// ---------------- recurrent step: fused 4-gate GEMM + LSTM update ----------------

__device__ __forceinline__ void gemm_phase(
    float (&acc)[16],
    const float* __restrict__ uBase, size_t uStride,
    const float* __restrict__ wBase, int wld, int nkt,
    float (*us)[64], float (*ws)[64], int tid)
{
    int tx = tid & 15, ty = tid >> 4;
    int lb = tid >> 2, lk4 = (tid & 3) << 2;
    int wk = tid >> 4, wj4 = (tid & 15) << 2;
    for (int kt = 0; kt < nkt; kt++) {
        int k0 = kt << 4;
        float4 uv = *(const float4*)(uBase + (size_t)lb * uStride + k0 + lk4);
        float4 wv = *(const float4*)(wBase + (size_t)(k0 + wk) * wld + wj4);
        __syncthreads();
        us[lk4 + 0][lb] = uv.x; us[lk4 + 1][lb] = uv.y;
        us[lk4 + 2][lb] = uv.z; us[lk4 + 3][lb] = uv.w;
        *(float4*)&ws[wk][wj4] = wv;
        __syncthreads();
#pragma unroll
        for (int k = 0; k < 16; k++) {
            float4 a = *(const float4*)&us[k][ty << 2];
            float4 b = *(const float4*)&ws[k][tx << 2];
            float av[4] = {a.x, a.y, a.z, a.w};
            float bv[4] = {b.x, b.y, b.z, b.w};
#pragma unroll
            for (int r = 0; r < 4; r++)
#pragma unroll
                for (int cc = 0; cc < 4; cc++)
                    acc[(r << 2) + cc] += av[r] * bv[cc];
        }
    }
}

__global__ void __launch_bounds__(256) k_step(int t) {
    __shared__ float us[16][64];
    __shared__ float ws[16][64];
    __shared__ float ws2[16][64];
    int tid = threadIdx.x;
    int tx = tid & 15, ty = tid >> 4;
    int bb = blockIdx.x << 6;
    int jj = blockIdx.y << 6;
    const float* __restrict__ hin = g_h[t & 1];
    float* __restrict__ hout = g_h[(t & 1) ^ 1];
    float acc_i[16], acc_f[16], acc_o[16], acc_g[16];
#pragma unroll
    for (int e = 0; e < 16; e++) { acc_i[e] = 0.f; acc_f[e] = 0.f; acc_o[e] = 0.f; acc_g[e] = 0.f; }

    int lb = tid >> 2, lk4 = (tid & 3) << 2, wk = tid >> 4, wj4 = (tid & 15) << 2;

    // Phase A: enc (K=64) -> gate i and x-part of gate f (shared u tile)
    {
        const float* uBase = g_enc + ((size_t)bb * TSTEPS + t) * 64;
        for (int kt = 0; kt < 4; kt++) {
            int k0 = kt << 4;
            float4 uv  = *(const float4*)(uBase + (size_t)lb * (TSTEPS * 64) + k0 + lk4);
            float4 w1v = *(const float4*)(g_Q + (size_t)(k0 + wk) * 4096 + jj + wj4);
            float4 w2v = *(const float4*)(g_Q + (size_t)(k0 + wk) * 4096 + 2048 + jj + wj4);
            __syncthreads();
            us[lk4 + 0][lb] = uv.x; us[lk4 + 1][lb] = uv.y;
            us[lk4 + 2][lb] = uv.z; us[lk4 + 3][lb] = uv.w;
            *(float4*)&ws[wk][wj4] = w1v;
            *(float4*)&ws2[wk][wj4] = w2v;
            __syncthreads();
#pragma unroll
            for (int k = 0; k < 16; k++) {
                float4 a  = *(const float4*)&us[k][ty << 2];
                float4 b  = *(const float4*)&ws[k][tx << 2];
                float4 b2 = *(const float4*)&ws2[k][tx << 2];
                float av[4] = {a.x, a.y, a.z, a.w};
                float bv[4] = {b.x, b.y, b.z, b.w};
                float cv[4] = {b2.x, b2.y, b2.z, b2.w};
#pragma unroll
                for (int r = 0; r < 4; r++)
#pragma unroll
                    for (int cc = 0; cc < 4; cc++) {
                        acc_i[(r << 2) + cc] += av[r] * bv[cc];
                        acc_f[(r << 2) + cc] += av[r] * cv[cc];
                    }
            }
        }
    }
    // Phase B: h[0:512]    -> gate f
    gemm_phase(acc_f, hin + (size_t)bb * 2048 + 0,    2048, g_Wf + jj, 2048, 32, us, ws, tid);
    // Phase C: h[512:1280] -> gate o
    gemm_phase(acc_o, hin + (size_t)bb * 2048 + 512,  2048, g_Wo + jj, 2048, 48, us, ws, tid);
    // Phase D: h[1280:2048]-> gate g
    gemm_phase(acc_g, hin + (size_t)bb * 2048 + 1280, 2048, g_Wg + jj, 2048, 48, us, ws, tid);

    // LSTM update (fused; no gate traffic to DRAM)
#pragma unroll
    for (int r = 0; r < 4; r++) {
        int b = bb + (ty << 2) + r;
#pragma unroll
        for (int cc = 0; cc < 4; cc++) {
            int j = jj + (tx << 2) + cc;
            int e = (r << 2) + cc;
            float pi = acc_i[e] + g_bias_if[j];
            float pf = acc_f[e] + g_bias_if[2048 + j];
            float po = acc_o[e] + g_bias_o[j];
            float pg = acc_g[e] + g_bias_g[j];
            size_t off = (size_t)b * 2048 + j;
            float si = 1.f / (1.f + __expf(-pi));
            float sf = 1.f / (1.f + __expf(-pf));
            float so = 1.f / (1.f + __expf(-po));
            float tg = 2.f / (1.f + __expf(-2.f * pg)) - 1.f;
            float cn = sf * g_c[off] + si * tg;
            g_c[off] = cn;
            float tc = 2.f / (1.f + __expf(-2.f * cn)) - 1.f;
            hout[off] = so * tc;
        }
    }
}

// ---------------- classifier ----------------

__global__ void k_cls1(const float* __restrict__ w, const float* __restrict__ bias) {
    __shared__ float sf[16][64];
    __shared__ float sw[64][129];
    const float* hptr = g_h[0];
    int tid = threadIdx.x;   // = output channel
    int b0 = blockIdx.x * 16;
    float acc[16];
#pragma unroll
    for (int r = 0; r < 16; r++) acc[r] = 0.f;
    for (int k0 = 0; k0 < 2048; k0 += 64) {
        __syncthreads();
        for (int i = tid; i < 16 * 64; i += 128) {
            int r = i / 64, kl = i % 64;
            sf[r][kl] = hptr[(size_t)(b0 + r) * 2048 + k0 + kl];
        }
        {
            int kl = tid % 64, og = tid / 64;
            for (int o = og; o < 128; o += 2)
                sw[kl][o] = w[(size_t)o * 2048 + k0 + kl];
        }
        __syncthreads();
        for (int kl = 0; kl < 64; kl++) {
            float wv = sw[kl][tid];
#pragma unroll
            for (int r = 0; r < 16; r++) acc[r] += sf[r][kl] * wv;
        }
    }
    for (int r = 0; r < 16; r++)
        g_hid[(size_t)(b0 + r) * 128 + tid] = fmaxf(acc[r] + bias[tid], 0.f);
}

__global__ void k_cls2(const float* __restrict__ w, const float* __restrict__ b,
                       float* __restrict__ out) {
    int bi = blockIdx.x * blockDim.x + threadIdx.x;
    if (bi >= BATCH) return;
    float a0 = b[0], a1 = b[1];
    for (int k = 0; k < 128; k++) {
        float h = g_hid[(size_t)bi * 128 + k];
        a0 += h * w[k];
        a1 += h * w[128 + k];
    }
    out[bi * 2 + 0] = a0;
    out[bi * 2 + 1] = a1;
}

// ---------------- launch ----------------

extern "C" void kernel_launch(void* const* d_in, const int* in_sizes, int n_in,
                              void* d_out, int out_size) {
    const float* x        = (const float*)d_in[0];
    const float* conv1d_w = (const float*)d_in[1];
    const float* conv1d_b = (const float*)d_in[2];
    const float* bn_gamma = (const float*)d_in[3];
    const float* bn_beta  = (const float*)d_in[4];
    const float* bn_mean  = (const float*)d_in[5];
    const float* bn_var   = (const float*)d_in[6];
    const float* lin_w    = (const float*)d_in[7];
    const float* lin_b    = (const float*)d_in[8];
    const float* cell_w   = (const float*)d_in[9];
    const float* cell_b   = (const float*)d_in[10];
    const float* cls1_w   = (const float*)d_in[11];
    const float* cls1_b   = (const float*)d_in[12];
    const float* cls2_w   = (const float*)d_in[13];
    const float* cls2_b   = (const float*)d_in[14];
    float* out = (float*)d_out;

    k_prep_w1<<<(FEAT * 64 + 255) / 256, 256>>>(conv1d_w, conv1d_b, bn_gamma, bn_beta, bn_mean, bn_var);
    k_S<<<(1024 * 64 + 255) / 256, 256>>>(lin_w);
    k_buildQ<<<(4096 * 64 + 255) / 256, 256>>>(cell_w, cell_b, lin_b);
    k_buildWh<<<(int)(((size_t)2048 * 2048 + 255) / 256), 256>>>(cell_w, cell_b);
    k_enc<<<BT / 32, 256>>>(x);
    k_zero<<<(int)(((size_t)BATCH * 2048 + 255) / 256), 256>>>();

    for (int t = 0; t < TSTEPS; t++)
        k_step<<<dim3(BATCH / 64, 2048 / 64), 256>>>(t);

    k_cls1<<<BATCH / 16, 128>>>(cls1_w, cls1_b);
    k_cls2<<<(BATCH + 127) / 128, 128>>>(cls2_w, cls2_b, out);
}